// round 7
// baseline (speedup 1.0000x reference)
#include <cuda_runtime.h>

#define N_NODES   1000000
#define DIM       128
#define B_GRAPHS  2048
#define CROWS     96          // rows of pass-1 tail cached in smem for pass 2

// Scratch (no cudaMalloc allowed): transposed W for coalesced GEMM reads
__device__ float g_Wt[DIM * DIM];

// ---------------------------------------------------------------------------
// Kernel 0: transpose W (64KB).  g_Wt[k*DIM + j] = W[j*DIM + k]
// ---------------------------------------------------------------------------
__global__ void transpose_W_kernel(const float* __restrict__ W) {
    int i = blockIdx.x * blockDim.x + threadIdx.x;
    if (i < DIM * DIM) {
        int j = i >> 7;
        int k = i & (DIM - 1);
        g_Wt[k * DIM + j] = W[i];
    }
}

// ---------------------------------------------------------------------------
// Fused kernel: one block per graph. float4 lanes: 32 lanes cover one 512B row;
// 4 warps (subgroups) stride rows by 4. ~52KB smem caps occupancy at 4 blk/SM
// so the per-wave read set (~148MB) ~ fits L2, and the last CROWS rows are
// replayed from smem in pass 2 (reverse order) -> deterministic reuse.
// ---------------------------------------------------------------------------
__global__ void __launch_bounds__(128)
fused_vn_kernel(const float* __restrict__ h,
                const float* __restrict__ vn_h,
                const float* __restrict__ b,
                const int*   __restrict__ seg,
                float*       __restrict__ vn_out,
                float*       __restrict__ h_out) {
    __shared__ float4 scache[CROWS * 32];   // 49152 B row cache
    __shared__ float  spool[4][DIM];        // per-subgroup partial sums
    __shared__ float  sx[DIM];              // GEMM input row
    __shared__ float  svn[DIM];             // final vn row
    __shared__ int    sbounds[2];

    int g  = blockIdx.x;
    int t  = threadIdx.x;
    int sg = t >> 5;          // row subgroup (warp) 0..3
    int ln = t & 31;          // float4 lane within row

    // --- bounds via binary search (sorted seg ids -> contiguous range)
    if (t < 2) {
        int target = g + t;
        int lo = 0, hi = N_NODES;
        while (lo < hi) {
            int mid = (lo + hi) >> 1;
            if (__ldg(&seg[mid]) < target) lo = mid + 1;
            else                           hi = mid;
        }
        sbounds[t] = lo;
    }
    __syncthreads();
    int start = sbounds[0];
    int end   = sbounds[1];
    int cbase = end - CROWS; if (cbase < start) cbase = start;

    const float4* h4 = (const float4*)h;

    // --- pass 1: segment sum, LDG.128, warp w handles rows r = start+w+4k
    float4 a = make_float4(0.f, 0.f, 0.f, 0.f);
    int r = start + sg;
    #pragma unroll 8
    for (; r < cbase; r += 4) {
        float4 v = __ldg(&h4[r * 32 + ln]);
        a.x += v.x; a.y += v.y; a.z += v.z; a.w += v.w;
    }
    #pragma unroll 4
    for (; r < end; r += 4) {                      // tail rows: also cache in smem
        float4 v = __ldg(&h4[r * 32 + ln]);
        scache[(r - cbase) * 32 + ln] = v;
        a.x += v.x; a.y += v.y; a.z += v.z; a.w += v.w;
    }

    // --- reduce 4 subgroup partials -> pool[t]
    ((float4*)&spool[sg][0])[ln] = a;
    __syncthreads();
    float pool = spool[0][t] + spool[1][t] + spool[2][t] + spool[3][t];

    // --- VN update: vn = vn_h + relu((vn_h + pool) @ W^T + b)
    float vh = __ldg(&vn_h[g * DIM + t]);
    sx[t] = vh + pool;
    __syncthreads();

    float acc0 = 0.f, acc1 = 0.f;
    #pragma unroll 8
    for (int k = 0; k < DIM; k += 2) {
        acc0 = fmaf(sx[k],     __ldg(&g_Wt[k * DIM + t]),       acc0);
        acc1 = fmaf(sx[k + 1], __ldg(&g_Wt[(k + 1) * DIM + t]), acc1);
    }
    float vn = vh + fmaxf(acc0 + acc1 + __ldg(&b[t]), 0.f);
    vn_out[g * DIM + t] = vn;
    svn[t] = vn;
    __syncthreads();

    float4 vnv = ((const float4*)svn)[ln];         // this lane's 4 columns

    // --- pass 2 (reverse): h_out = h + vn. Tail rows from smem, rest via .cs
    float4* o4 = (float4*)h_out;
    int cnt = end - (start + sg);
    if (cnt > 0) {
        int rr = start + sg + ((cnt - 1) >> 2) * 4;    // this sg's last row
        #pragma unroll 4
        for (; rr >= cbase; rr -= 4) {                 // smem-cached region
            float4 v = scache[(rr - cbase) * 32 + ln];
            __stcs(&o4[rr * 32 + ln],
                   make_float4(v.x + vnv.x, v.y + vnv.y, v.z + vnv.z, v.w + vnv.w));
        }
        #pragma unroll 8
        for (; rr >= start; rr -= 4) {                 // L2/DRAM region, evict-first
            float4 v = __ldcs(&h4[rr * 32 + ln]);
            __stcs(&o4[rr * 32 + ln],
                   make_float4(v.x + vnv.x, v.y + vnv.y, v.z + vnv.z, v.w + vnv.w));
        }
    }
}

// ---------------------------------------------------------------------------
// Launch: out = [vn_out (B*DIM floats) | h_out (N*DIM floats)]
// ---------------------------------------------------------------------------
extern "C" void kernel_launch(void* const* d_in, const int* in_sizes, int n_in,
                              void* d_out, int out_size) {
    const float* h    = (const float*)d_in[0];
    const float* vn_h = (const float*)d_in[1];
    const float* W    = (const float*)d_in[2];
    const float* b    = (const float*)d_in[3];
    const int*   seg  = (const int*)  d_in[4];

    float* out    = (float*)d_out;
    float* vn_out = out;                       // [B, DIM]
    float* h_out  = out + B_GRAPHS * DIM;      // [N, DIM]

    transpose_W_kernel<<<(DIM * DIM + 255) / 256, 256>>>(W);
    fused_vn_kernel<<<B_GRAPHS, DIM>>>(h, vn_h, b, seg, vn_out, h_out);
}

// round 8
// speedup vs baseline: 1.3681x; 1.3681x over previous
#include <cuda_runtime.h>

#define N_NODES   1000000
#define DIM       128
#define B_GRAPHS  2048

// Scratch (no cudaMalloc allowed): transposed W for coalesced GEMM reads
__device__ float g_Wt[DIM * DIM];

// ---------------------------------------------------------------------------
// Kernel 0: transpose W (64KB).  g_Wt[k*DIM + j] = W[j*DIM + k]
// ---------------------------------------------------------------------------
__global__ void transpose_W_kernel(const float* __restrict__ W) {
    int i = blockIdx.x * blockDim.x + threadIdx.x;
    if (i < DIM * DIM) {
        int j = i >> 7;
        int k = i & (DIM - 1);
        g_Wt[k * DIM + j] = W[i];
    }
}

// ---------------------------------------------------------------------------
// Fused kernel: one block per graph (sorted seg ids -> contiguous range).
// float4 lanes: 32 lanes cover one 512B row; 4 warps stride rows by 4.
// High occupancy (tiny smem, low regs) + LDG.128 for max bytes in flight.
// Pass 2 reversed with .cs hints: most-recently-read pass-1 lines hit L2,
// and streaming stores don't pollute it.
// ---------------------------------------------------------------------------
__global__ void __launch_bounds__(128)
fused_vn_kernel(const float* __restrict__ h,
                const float* __restrict__ vn_h,
                const float* __restrict__ b,
                const int*   __restrict__ seg,
                float*       __restrict__ vn_out,
                float*       __restrict__ h_out) {
    __shared__ float spool[4][DIM];   // per-warp partial sums
    __shared__ float sx[DIM];         // GEMM input row
    __shared__ float svn[DIM];        // final vn row
    __shared__ int   sbounds[2];

    int g  = blockIdx.x;
    int t  = threadIdx.x;
    int sg = t >> 5;                  // warp 0..3 (row subgroup)
    int ln = t & 31;                  // float4 lane within row

    // --- bounds via binary search
    if (t < 2) {
        int target = g + t;
        int lo = 0, hi = N_NODES;
        while (lo < hi) {
            int mid = (lo + hi) >> 1;
            if (__ldg(&seg[mid]) < target) lo = mid + 1;
            else                           hi = mid;
        }
        sbounds[t] = lo;
    }
    __syncthreads();
    int start = sbounds[0];
    int end   = sbounds[1];

    const float4* h4 = (const float4*)h;

    // --- pass 1: segment sum, LDG.128, warp sg handles rows start+sg, +4, ...
    float4 a = make_float4(0.f, 0.f, 0.f, 0.f);
    #pragma unroll 8
    for (int r = start + sg; r < end; r += 4) {
        float4 v = __ldg(&h4[r * 32 + ln]);
        a.x += v.x; a.y += v.y; a.z += v.z; a.w += v.w;
    }

    // --- reduce 4 warp partials -> pool[t]
    ((float4*)&spool[sg][0])[ln] = a;
    __syncthreads();
    float pool = spool[0][t] + spool[1][t] + spool[2][t] + spool[3][t];

    // --- VN update: vn = vn_h + relu((vn_h + pool) @ W^T + b)
    float vh = __ldg(&vn_h[g * DIM + t]);
    sx[t] = vh + pool;
    __syncthreads();

    float acc0 = 0.f, acc1 = 0.f;
    #pragma unroll 8
    for (int k = 0; k < DIM; k += 2) {
        acc0 = fmaf(sx[k],     __ldg(&g_Wt[k * DIM + t]),       acc0);
        acc1 = fmaf(sx[k + 1], __ldg(&g_Wt[(k + 1) * DIM + t]), acc1);
    }
    float vn = vh + fmaxf(acc0 + acc1 + __ldg(&b[t]), 0.f);
    vn_out[g * DIM + t] = vn;
    svn[t] = vn;
    __syncthreads();

    float4 vnv = ((const float4*)svn)[ln];      // this lane's 4 columns of vn

    // --- pass 2 (reverse): h_out = h + vn, streaming hints
    float4* o4 = (float4*)h_out;
    int cnt = end - (start + sg);
    if (cnt > 0) {
        int rr = start + sg + ((cnt - 1) >> 2) * 4;   // this warp's last row
        #pragma unroll 8
        for (; rr >= start; rr -= 4) {
            float4 v = __ldcs(&h4[rr * 32 + ln]);
            __stcs(&o4[rr * 32 + ln],
                   make_float4(v.x + vnv.x, v.y + vnv.y,
                               v.z + vnv.z, v.w + vnv.w));
        }
    }
}

// ---------------------------------------------------------------------------
// Launch: out = [vn_out (B*DIM floats) | h_out (N*DIM floats)]
// ---------------------------------------------------------------------------
extern "C" void kernel_launch(void* const* d_in, const int* in_sizes, int n_in,
                              void* d_out, int out_size) {
    const float* h    = (const float*)d_in[0];
    const float* vn_h = (const float*)d_in[1];
    const float* W    = (const float*)d_in[2];
    const float* b    = (const float*)d_in[3];
    const int*   seg  = (const int*)  d_in[4];

    float* out    = (float*)d_out;
    float* vn_out = out;                       // [B, DIM]
    float* h_out  = out + B_GRAPHS * DIM;      // [N, DIM]

    transpose_W_kernel<<<(DIM * DIM + 255) / 256, 256>>>(W);
    fused_vn_kernel<<<B_GRAPHS, DIM>>>(h, vn_h, b, seg, vn_out, h_out);
}

// round 9
// speedup vs baseline: 1.4156x; 1.0348x over previous
#include <cuda_runtime.h>
#include <cstdint>

#define N_NODES   1000000
#define DIM       128
#define B_GRAPHS  2048
#define CROWS     32                 // rows per pipeline chunk
#define ROWB      512                // bytes per row (128 fp32)
#define CBYTES    (CROWS * ROWB)     // 16 KB

// Scratch (no cudaMalloc allowed): transposed W for coalesced GEMM reads
__device__ float g_Wt[DIM * DIM];

__global__ void transpose_W_kernel(const float* __restrict__ W) {
    int i = blockIdx.x * blockDim.x + threadIdx.x;
    if (i < DIM * DIM) {
        int j = i >> 7;
        int k = i & (DIM - 1);
        g_Wt[k * DIM + j] = W[i];
    }
}

// ---- TMA / mbarrier helpers (1D bulk copies, no tensor map needed) --------
__device__ __forceinline__ uint32_t s2u(const void* p) {
    return (uint32_t)__cvta_generic_to_shared(p);
}
__device__ __forceinline__ void mbar_init1(uint32_t a) {
    asm volatile("mbarrier.init.shared.b64 [%0], 1;" :: "r"(a) : "memory");
}
__device__ __forceinline__ void tma_fetch(uint32_t mbar, uint32_t dst,
                                          const void* src, uint32_t bytes) {
    asm volatile("mbarrier.arrive.expect_tx.shared.b64 _, [%0], %1;"
                 :: "r"(mbar), "r"(bytes) : "memory");
    asm volatile("cp.async.bulk.shared::cta.global.mbarrier::complete_tx::bytes "
                 "[%0], [%1], %2, [%3];"
                 :: "r"(dst), "l"(src), "r"(bytes), "r"(mbar) : "memory");
}
__device__ __forceinline__ void mbar_wait(uint32_t a, uint32_t parity) {
    asm volatile(
        "{\n\t.reg .pred P;\n"
        "W%=:\n\t"
        "mbarrier.try_wait.parity.acquire.cta.shared::cta.b64 P, [%0], %1, 0x989680;\n\t"
        "@P bra D%=;\n\t"
        "bra W%=;\n"
        "D%=:\n\t}"
        :: "r"(a), "r"(parity) : "memory");
}

// ---------------------------------------------------------------------------
// Fused kernel: one block per graph (sorted seg -> contiguous row range).
// Double-buffered TMA pipeline (2 x 16KB): bulk copies supply 192KB/SM of
// in-flight DRAM traffic independent of warp count / registers.
//   pass 1: stream chunks fwd, sum columns from smem      (read h)
//   GEMM:   vn = vn_h + relu((vn_h + pool) @ W^T + b)
//   pass 2: stream chunks in REVERSE (L2 tail reuse), add vn, STG.128 .cs
// ---------------------------------------------------------------------------
__global__ void __launch_bounds__(128)
fused_vn_kernel(const float* __restrict__ h,
                const float* __restrict__ vn_h,
                const float* __restrict__ bias,
                const int*   __restrict__ seg,
                float*       __restrict__ vn_out,
                float*       __restrict__ h_out) {
    __shared__ __align__(1024) float4 sbuf[2][CROWS * 32];   // 2 x 16 KB
    __shared__ float spool[4][DIM];
    __shared__ float sx[DIM];
    __shared__ float svn[DIM];
    __shared__ int   sbounds[2];
    __shared__ __align__(8) unsigned long long smbar[2];

    const int g  = blockIdx.x;
    const int t  = threadIdx.x;
    const int sg = t >> 5;      // warp = row subgroup
    const int ln = t & 31;      // float4 lane within a row

    if (t < 2) {                // bounds via binary search
        int target = g + t, lo = 0, hi = N_NODES;
        while (lo < hi) {
            int mid = (lo + hi) >> 1;
            if (__ldg(&seg[mid]) < target) lo = mid + 1;
            else                           hi = mid;
        }
        sbounds[t] = lo;
    }
    uint32_t mb[2]   = { s2u(&smbar[0]),   s2u(&smbar[1]) };
    uint32_t bufa[2] = { s2u(&sbuf[0][0]), s2u(&sbuf[1][0]) };
    if (t == 0) {
        mbar_init1(mb[0]);
        mbar_init1(mb[1]);
        asm volatile("fence.proxy.async.shared::cta;" ::: "memory");
    }
    __syncthreads();

    const int start = sbounds[0], end = sbounds[1];
    const int rows  = end - start;
    const int nc    = (rows + CROWS - 1) / CROWS;
    const char* gsrc = (const char*)h + (size_t)start * ROWB;
    int kb0 = 0, kb1 = 0;       // per-buffer mbarrier phase counters

    // --- pass 1 prologue
    if (t == 0) {
        if (nc > 0) tma_fetch(mb[0], bufa[0], gsrc,
                              (uint32_t)min(CROWS, rows) * ROWB);
        if (nc > 1) tma_fetch(mb[1], bufa[1], gsrc + CBYTES,
                              (uint32_t)min(CROWS, rows - CROWS) * ROWB);
    }

    // --- pass 1: segment sum from smem chunks
    float4 a = make_float4(0.f, 0.f, 0.f, 0.f);
    for (int c = 0; c < nc; ++c) {
        int bs = c & 1;
        if (bs) { mbar_wait(mb[1], kb1 & 1); ++kb1; }
        else    { mbar_wait(mb[0], kb0 & 1); ++kb0; }
        int rn = min(CROWS, rows - c * CROWS);
        const float4* sb = sbuf[bs];
        #pragma unroll
        for (int r = sg; r < CROWS; r += 4) {
            if (r < rn) {
                float4 v = sb[r * 32 + ln];
                a.x += v.x; a.y += v.y; a.z += v.z; a.w += v.w;
            }
        }
        __syncthreads();                      // buffer free for refill
        if (t == 0 && c + 2 < nc) {
            int cc = c + 2;
            tma_fetch(mb[bs], bufa[bs], gsrc + (size_t)cc * CBYTES,
                      (uint32_t)min(CROWS, rows - cc * CROWS) * ROWB);
        }
    }

    // --- reduce warp partials -> pool
    ((float4*)&spool[sg][0])[ln] = a;
    __syncthreads();
    float pool = spool[0][t] + spool[1][t] + spool[2][t] + spool[3][t];

    float vh = __ldg(&vn_h[g * DIM + t]);
    sx[t] = vh + pool;
    __syncthreads();

    // --- pass 2 prologue issued early: overlap fetch with GEMM
    if (t == 0) {
        if (nc > 0) {
            int c = nc - 1;
            tma_fetch(mb[0], bufa[0], gsrc + (size_t)c * CBYTES,
                      (uint32_t)(rows - c * CROWS) * ROWB);
        }
        if (nc > 1) {
            int c = nc - 2;
            tma_fetch(mb[1], bufa[1], gsrc + (size_t)c * CBYTES, CBYTES);
        }
    }

    // --- VN GEMM: vn = vn_h + relu(sx @ W^T + b)
    float acc0 = 0.f, acc1 = 0.f;
    #pragma unroll 8
    for (int k = 0; k < DIM; k += 2) {
        acc0 = fmaf(sx[k],     __ldg(&g_Wt[k * DIM + t]),       acc0);
        acc1 = fmaf(sx[k + 1], __ldg(&g_Wt[(k + 1) * DIM + t]), acc1);
    }
    float vn = vh + fmaxf(acc0 + acc1 + __ldg(&bias[t]), 0.f);
    vn_out[g * DIM + t] = vn;
    svn[t] = vn;
    __syncthreads();
    float4 vnv = ((const float4*)svn)[ln];

    // --- pass 2: reverse chunk order, h_out = h + vn, streaming stores
    float4* o4 = (float4*)h_out;
    for (int j = 0; j < nc; ++j) {
        int c  = nc - 1 - j;
        int bs = j & 1;
        if (bs) { mbar_wait(mb[1], kb1 & 1); ++kb1; }
        else    { mbar_wait(mb[0], kb0 & 1); ++kb0; }
        int rn = min(CROWS, rows - c * CROWS);
        const float4* sb = sbuf[bs];
        size_t obase = (size_t)(start + c * CROWS) * 32;
        #pragma unroll
        for (int r = sg; r < CROWS; r += 4) {
            if (r < rn) {
                float4 v = sb[r * 32 + ln];
                __stcs(&o4[obase + r * 32 + ln],
                       make_float4(v.x + vnv.x, v.y + vnv.y,
                                   v.z + vnv.z, v.w + vnv.w));
            }
        }
        __syncthreads();
        if (t == 0 && j + 2 < nc) {
            int cc = nc - 1 - (j + 2);      // cc <= nc-3 -> always a full chunk
            tma_fetch(mb[bs], bufa[bs], gsrc + (size_t)cc * CBYTES, CBYTES);
        }
    }
}

// ---------------------------------------------------------------------------
// Launch: out = [vn_out (B*DIM floats) | h_out (N*DIM floats)]
// ---------------------------------------------------------------------------
extern "C" void kernel_launch(void* const* d_in, const int* in_sizes, int n_in,
                              void* d_out, int out_size) {
    const float* h    = (const float*)d_in[0];
    const float* vn_h = (const float*)d_in[1];
    const float* W    = (const float*)d_in[2];
    const float* b    = (const float*)d_in[3];
    const int*   seg  = (const int*)  d_in[4];

    float* out    = (float*)d_out;
    float* vn_out = out;                       // [B, DIM]
    float* h_out  = out + B_GRAPHS * DIM;      // [N, DIM]

    transpose_W_kernel<<<(DIM * DIM + 255) / 256, 256>>>(W);
    fused_vn_kernel<<<B_GRAPHS, DIM>>>(h, vn_h, b, seg, vn_out, h_out);
}